// round 2
// baseline (speedup 1.0000x reference)
#include <cuda_runtime.h>
#include <math.h>

#define BB 64
#define DIM 640
#define MK 100
#define TT 128
#define NT 5          // DIM / TT
#define NPAIR 15      // NT*(NT+1)/2 upper tile pairs
#define PADK 136      // smem row pad (mult of 4, stride mod 32 = 8 -> 4-way store conflicts only)
#define TRI 205120    // 640*641/2
#define EPSV 1e-5f

// Scratch (static __device__ arrays: allocation-free per harness rules)
__device__ float g_dcov[(size_t)BB * DIM * DIM];  // ~104.9 MB, only upper tiles written
__device__ float g_d[BB * DIM];                   // squared norms
__device__ float g_s[BB * DIM];                   // row sums of dcov (== col sums, symmetric)

// ---------------------------------------------------------------------------
// Kernel 0: squared norms + zero row-sum accumulators
// ---------------------------------------------------------------------------
__global__ void prep_kernel(const float* __restrict__ x) {
    int idx = blockIdx.x * 256 + threadIdx.x;
    if (idx >= BB * DIM) return;
    const float4* xr = (const float4*)(x + (size_t)idx * MK);  // 400B rows -> 16B aligned
    float s = 0.f;
#pragma unroll
    for (int m = 0; m < MK / 4; m++) {
        float4 v = xr[m];
        s += v.x * v.x + v.y * v.y + v.z * v.z + v.w * v.w;
    }
    g_d[idx] = s;
    g_s[idx] = 0.f;
}

// ---------------------------------------------------------------------------
// Kernel 1: per (batch, upper tile pair): Gram -> dcov -> scratch + row sums
// 256 threads, 8x8 micro-tile per thread, full K=100 staged in smem [k][row].
// ---------------------------------------------------------------------------
__global__ __launch_bounds__(256, 2)
void gram_dcov_kernel(const float* __restrict__ x, const float* __restrict__ t) {
    int p = blockIdx.x, b = blockIdx.y;
    int ti = 0, rem = p;
    while (rem >= NT - ti) { rem -= NT - ti; ti++; }
    int tj = ti + rem;
    int i0 = ti * TT, j0 = tj * TT;

    extern __shared__ float sm[];
    float* As = sm;               // [MK][PADK]
    float* Bs = sm + MK * PADK;   // [MK][PADK]

    const float* xb = x + (size_t)b * DIM * MK;
    int tid = threadIdx.x;

    // Stage tiles transposed: As[m][r] = x[b][i0+r][m]  (coalesced global reads)
    for (int idx = tid; idx < TT * MK; idx += 256) {
        int r = idx / MK, m = idx - r * MK;
        As[m * PADK + r] = xb[(i0 + r) * MK + m];
    }
    if (tj != ti) {
        for (int idx = tid; idx < TT * MK; idx += 256) {
            int r = idx / MK, m = idx - r * MK;
            Bs[m * PADK + r] = xb[(j0 + r) * MK + m];
        }
    }
    __syncthreads();
    const float* Bp = (ti == tj) ? As : Bs;

    int tx = tid & 15;   // j-dir: 16 groups of 8
    int ty = tid >> 4;   // i-dir: 16 groups of 8

    float acc[8][8];
#pragma unroll
    for (int r = 0; r < 8; r++)
#pragma unroll
        for (int c = 0; c < 8; c++) acc[r][c] = 0.f;

    const float* ap = As + ty * 8;
    const float* bp = Bp + tx * 8;

#pragma unroll 2
    for (int k = 0; k < MK; k++) {
        float4 A0 = *(const float4*)(ap + k * PADK);
        float4 A1 = *(const float4*)(ap + k * PADK + 4);
        float4 B0 = *(const float4*)(bp + k * PADK);
        float4 B1 = *(const float4*)(bp + k * PADK + 4);
        float av[8] = {A0.x, A0.y, A0.z, A0.w, A1.x, A1.y, A1.z, A1.w};
        float bv[8] = {B0.x, B0.y, B0.z, B0.w, B1.x, B1.y, B1.z, B1.w};
#pragma unroll
        for (int r = 0; r < 8; r++)
#pragma unroll
            for (int c = 0; c < 8; c++)
                acc[r][c] = fmaf(av[r], bv[c], acc[r][c]);
    }

    // Epilogue: dcov = sqrt(et * max(d_i + d_j - 2G, 0) + eps)
    float et = expf(t[0]);
    const float* dbase = g_d + b * DIM;
    float di[8], dj[8];
#pragma unroll
    for (int r = 0; r < 8; r++) di[r] = dbase[i0 + ty * 8 + r];
#pragma unroll
    for (int c = 0; c < 8; c++) dj[c] = dbase[j0 + tx * 8 + c];

    float rs[8], cs[8];
#pragma unroll
    for (int r = 0; r < 8; r++) rs[r] = 0.f;
#pragma unroll
    for (int c = 0; c < 8; c++) cs[c] = 0.f;

    float* dst = g_dcov + ((size_t)b * DIM + i0 + ty * 8) * DIM + j0 + tx * 8;

#pragma unroll
    for (int r = 0; r < 8; r++) {
        float vv[8];
#pragma unroll
        for (int c = 0; c < 8; c++) {
            float q = fmaf(-2.f, acc[r][c], di[r] + dj[c]);
            q = fmaxf(q, 0.f);
            float v = sqrtf(fmaf(et, q, EPSV));
            vv[c] = v;
            rs[r] += v;
            cs[c] += v;
        }
        *(float4*)(dst + (size_t)r * DIM)     = make_float4(vv[0], vv[1], vv[2], vv[3]);
        *(float4*)(dst + (size_t)r * DIM + 4) = make_float4(vv[4], vv[5], vv[6], vv[7]);
    }

    // Row sums: reduce over tx (lanes 0-15 / 16-31 are distinct ty halves)
#pragma unroll
    for (int r = 0; r < 8; r++) {
        float v = rs[r];
#pragma unroll
        for (int o = 8; o >= 1; o >>= 1) v += __shfl_xor_sync(0xffffffffu, v, o);
        if (tx == 0) atomicAdd(&g_s[b * DIM + i0 + ty * 8 + r], v);
    }
    // Mirrored col sums for off-diagonal tiles (dcov symmetric)
    if (ti != tj) {
#pragma unroll
        for (int c = 0; c < 8; c++) {
            float v = cs[c] + __shfl_xor_sync(0xffffffffu, cs[c], 16);
            if (((tid & 31) >> 4) == 0)  // lanes 0-15 hold the warp partial
                atomicAdd(&g_s[b * DIM + j0 + tx * 8 + c], v);
        }
    }
}

// ---------------------------------------------------------------------------
// Kernel 2: double centering + triu extraction (row-major, coalesced writes)
// ---------------------------------------------------------------------------
__global__ __launch_bounds__(256)
void center_kernel(float* __restrict__ out) {
    int p = blockIdx.x, b = blockIdx.y;
    int ti = 0, rem = p;
    while (rem >= NT - ti) { rem -= NT - ti; ti++; }
    int tj = ti + rem;
    int i0 = ti * TT, j0 = tj * TT;
    int tid = threadIdx.x;

    __shared__ float red[256];
    const float* sb = g_s + b * DIM;
    float ss = 0.f;
    for (int i = tid; i < DIM; i += 256) ss += sb[i];
    red[tid] = ss;
    __syncthreads();
    for (int o = 128; o > 0; o >>= 1) {
        if (tid < o) red[tid] += red[tid + o];
        __syncthreads();
    }
    float gm = red[0] * (1.0f / ((float)DIM * (float)DIM));
    const float invd = 1.0f / (float)DIM;

    const float* dc = g_dcov + (size_t)b * DIM * DIM;
    float* ob = out + (size_t)b * TRI;

    for (int idx = tid; idx < TT * TT; idx += 256) {
        int li = idx >> 7, lj = idx & 127;
        int i = i0 + li, j = j0 + lj;
        if (j < i) continue;
        float v = dc[(size_t)i * DIM + j] - (sb[i] + sb[j]) * invd + gm;
        size_t base = (size_t)i * DIM - ((size_t)i * (i - 1)) / 2;
        ob[base + (j - i)] = v;
    }
}

// ---------------------------------------------------------------------------
extern "C" void kernel_launch(void* const* d_in, const int* in_sizes, int n_in,
                              void* d_out, int out_size) {
    const float* x = (const float*)d_in[0];
    const float* t = (const float*)d_in[1];
    float* out = (float*)d_out;

    const int smem1 = 2 * MK * PADK * (int)sizeof(float);  // 108800 B
    cudaFuncSetAttribute(gram_dcov_kernel,
                         cudaFuncAttributeMaxDynamicSharedMemorySize, smem1);

    prep_kernel<<<(BB * DIM + 255) / 256, 256>>>(x);
    gram_dcov_kernel<<<dim3(NPAIR, BB), 256, smem1>>>(x, t);
    center_kernel<<<dim3(NPAIR, BB), 256>>>(out);
}